// round 5
// baseline (speedup 1.0000x reference)
#include <cuda_runtime.h>
#include <cuda_bf16.h>
#include <mma.h>

using namespace nvcuda;

#define NN 100000
#define NE 500000
#define MPAD 100096          // 782 * 128, padded row count for guard-free GEMM
#define FMAX 768

// ---------------- scratch (device globals: allowed; no cudaMalloc) ----------
__device__ __align__(16) float g_bufA[(size_t)MPAD * FMAX];
__device__ __align__(16) float g_bufB[(size_t)MPAD * FMAX];
__device__ float g_dinv[NN];
__device__ int   g_cnt[NN];
__device__ int   g_fill[NN];
__device__ int   g_rowptr[NN + 1];
__device__ int   g_col[NE];
__device__ float g_w[NE];
__device__ int   g_is64;

// ---------------- edge-index dtype detection --------------------------------
// Reference says int64, but JAX without x64 silently produces int32. Detect on
// device: int32 data reinterpreted as int64 gives values >= 2^32 almost surely.
__global__ void detect_k(const long long* __restrict__ p) {
    if (threadIdx.x == 0 && blockIdx.x == 0) {
        int ok = 1;
        for (int i = 0; i < 256; i++) {
            long long v = p[i];
            if (v < 0 || v >= (long long)NN) { ok = 0; break; }
        }
        g_is64 = ok;
    }
}

__device__ __forceinline__ int edge_at(const void* p, int idx) {
    if (g_is64) return (int)((const long long*)p)[idx];
    return ((const int*)p)[idx];
}

// ---------------- CSR build --------------------------------------------------
__global__ void zero_k() {
    int i = blockIdx.x * blockDim.x + threadIdx.x;
    if (i < NN) { g_cnt[i] = 0; g_fill[i] = 0; }
}

__global__ void count_k(const void* __restrict__ ei) {
    int e = blockIdx.x * blockDim.x + threadIdx.x;
    if (e < NE) {
        int d = edge_at(ei, NE + e);   // dst row
        atomicAdd(&g_cnt[d], 1);
    }
}

__global__ void dinv_k() {
    int i = blockIdx.x * blockDim.x + threadIdx.x;
    if (i < NN) g_dinv[i] = rsqrtf((float)g_cnt[i] + 1.0f);  // +1 self-loop
}

// exclusive scan of g_cnt -> g_rowptr, single block of 1024 threads
__global__ void scan_k() {
    __shared__ int ssum[1024];
    const int T = 1024;
    int t = threadIdx.x;
    int chunk = (NN + T - 1) / T;            // 98
    int start = t * chunk;
    int end   = start + chunk; if (end > NN) end = NN;
    int s = 0;
    for (int i = start; i < end && i < NN; i++) s += g_cnt[i];
    ssum[t] = s;
    __syncthreads();
    for (int off = 1; off < T; off <<= 1) {
        int v = ssum[t];
        int add = (t >= off) ? ssum[t - off] : 0;
        __syncthreads();
        ssum[t] = v + add;
        __syncthreads();
    }
    int run = (t > 0) ? ssum[t - 1] : 0;     // exclusive prefix
    for (int i = start; i < end && i < NN; i++) { g_rowptr[i] = run; run += g_cnt[i]; }
    if (t == T - 1) g_rowptr[NN] = ssum[T - 1];
}

__global__ void fill_k(const void* __restrict__ ei) {
    int e = blockIdx.x * blockDim.x + threadIdx.x;
    if (e < NE) {
        int s = edge_at(ei, e);
        int d = edge_at(ei, NE + e);
        int pos = g_rowptr[d] + atomicAdd(&g_fill[d], 1);
        g_col[pos] = s;
        g_w[pos]   = g_dinv[s] * g_dinv[d];
    }
}

// ---------------- exact GELU -------------------------------------------------
__device__ __forceinline__ float geluf(float x) {
    return 0.5f * x * (1.0f + erff(x * 0.7071067811865475f));
}

// ---------------- pull-mode aggregation (one warp per node, no atomics) ------
// Y[i] = gelu?( (1/deg_i) * X[i] (+bias) + sum_{e: dst=i} w_e * X[src_e] )
template <int V>   // V float4 per lane; F = 128*V
__global__ void agg_kernel(const float* __restrict__ X, float* __restrict__ Y,
                           const float* __restrict__ bias, int doGelu) {
    const int F = 128 * V;
    int gw   = (blockIdx.x * blockDim.x + threadIdx.x) >> 5;
    int lane = threadIdx.x & 31;
    int nw   = (gridDim.x * blockDim.x) >> 5;
    for (int i = gw; i < NN; i += nw) {
        float d  = g_dinv[i];
        float sw = d * d;                    // 1/deg (self-loop norm)
        const float4* xi = (const float4*)(X + (size_t)i * F);
        float4 acc[V];
#pragma unroll
        for (int v = 0; v < V; v++) {
            float4 t = xi[lane + 32 * v];
            acc[v].x = t.x * sw; acc[v].y = t.y * sw;
            acc[v].z = t.z * sw; acc[v].w = t.w * sw;
        }
        if (bias) {
#pragma unroll
            for (int v = 0; v < V; v++) {
                float4 b = ((const float4*)bias)[lane + 32 * v];
                acc[v].x += b.x; acc[v].y += b.y; acc[v].z += b.z; acc[v].w += b.w;
            }
        }
        int e0 = g_rowptr[i], e1 = g_rowptr[i + 1];
        for (int e = e0; e < e1; e++) {
            int   s  = __ldg(&g_col[e]);
            float we = __ldg(&g_w[e]);
            const float4* xs = (const float4*)(X + (size_t)s * F);
#pragma unroll
            for (int v = 0; v < V; v++) {
                float4 t = xs[lane + 32 * v];
                acc[v].x += we * t.x; acc[v].y += we * t.y;
                acc[v].z += we * t.z; acc[v].w += we * t.w;
            }
        }
        if (doGelu) {
#pragma unroll
            for (int v = 0; v < V; v++) {
                acc[v].x = geluf(acc[v].x); acc[v].y = geluf(acc[v].y);
                acc[v].z = geluf(acc[v].z); acc[v].w = geluf(acc[v].w);
            }
        }
        float4* yi = (float4*)(Y + (size_t)i * F);
#pragma unroll
        for (int v = 0; v < V; v++) yi[lane + 32 * v] = acc[v];
    }
}

// ---------------- TF32 WMMA GEMM: C[MPAD,Nn] = A[MPAD,K] @ B[K,Nn] ----------
// Row-major A and B. M padded to MPAD so there are no guards. Nn % 128 == 0,
// K % 32 == 0 for all four layers. Register double-buffered mainloop: tile
// k+1 is prefetched into registers while tile k computes from smem, hiding
// L2/DRAM latency without extra shared memory. Optional fused bias + exact
// GELU epilogue via per-warp smem staging.
__global__ __launch_bounds__(256) void gemm_tf32(const float* __restrict__ A,
                                                 const float* __restrict__ B,
                                                 float* __restrict__ C,
                                                 int K, int Nn,
                                                 const float* __restrict__ bias,
                                                 int doGelu) {
    constexpr int BM = 128, BN = 128, BK = 32;
    __shared__ float As[BM][BK + 4];
    __shared__ float Bs[BK][BN + 4];
    __shared__ float St[8][16][20];          // per-warp 16x16 stage, ldm=20
    int bm = blockIdx.y, bn = blockIdx.x;
    int tid  = threadIdx.x;
    int wid  = tid >> 5;
    int lane = tid & 31;
    int warpM = wid >> 2;   // 0..1 (64 rows each)
    int warpN = wid & 3;    // 0..3 (32 cols each)

    wmma::fragment<wmma::accumulator, 16, 16, 8, float> acc[4][2];
#pragma unroll
    for (int i = 0; i < 4; i++)
#pragma unroll
        for (int j = 0; j < 2; j++) wmma::fill_fragment(acc[i][j], 0.0f);

    const float* Ab = A + (size_t)bm * BM * K;
    const float* Bb = B + (size_t)bn * BN;

    // per-thread tile slot addresses (fixed across iterations)
    int arA[4], acA[4], arB[4], acB[4];
#pragma unroll
    for (int i = 0; i < 4; i++) {
        int f = tid + i * 256;
        arA[i] = f >> 3;  acA[i] = (f & 7) << 2;
        arB[i] = f >> 5;  acB[i] = (f & 31) << 2;
    }

    float4 ra[4], rb[4];
    // prefetch tile 0
#pragma unroll
    for (int i = 0; i < 4; i++) {
        ra[i] = *(const float4*)(Ab + (size_t)arA[i] * K + acA[i]);
        rb[i] = *(const float4*)(Bb + (size_t)arB[i] * Nn + acB[i]);
    }

    for (int k0 = 0; k0 < K; k0 += BK) {
        // commit prefetched tile to smem
#pragma unroll
        for (int i = 0; i < 4; i++) {
            As[arA[i]][acA[i]]     = ra[i].x; As[arA[i]][acA[i] + 1] = ra[i].y;
            As[arA[i]][acA[i] + 2] = ra[i].z; As[arA[i]][acA[i] + 3] = ra[i].w;
            Bs[arB[i]][acB[i]]     = rb[i].x; Bs[arB[i]][acB[i] + 1] = rb[i].y;
            Bs[arB[i]][acB[i] + 2] = rb[i].z; Bs[arB[i]][acB[i] + 3] = rb[i].w;
        }
        __syncthreads();
        // issue prefetch for tile k0+BK (overlaps with compute below)
        if (k0 + BK < K) {
#pragma unroll
            for (int i = 0; i < 4; i++) {
                ra[i] = *(const float4*)(Ab + (size_t)arA[i] * K + (k0 + BK) + acA[i]);
                rb[i] = *(const float4*)(Bb + (size_t)(k0 + BK + arB[i]) * Nn + acB[i]);
            }
        }
#pragma unroll
        for (int kk = 0; kk < BK / 8; kk++) {
            wmma::fragment<wmma::matrix_a, 16, 16, 8, wmma::precision::tf32, wmma::row_major> af[4];
            wmma::fragment<wmma::matrix_b, 16, 16, 8, wmma::precision::tf32, wmma::row_major> bf[2];
#pragma unroll
            for (int i = 0; i < 4; i++) {
                wmma::load_matrix_sync(af[i], &As[warpM * 64 + i * 16][kk * 8], BK + 4);
#pragma unroll
                for (int t = 0; t < af[i].num_elements; t++)
                    af[i].x[t] = wmma::__float_to_tf32(af[i].x[t]);
            }
#pragma unroll
            for (int j = 0; j < 2; j++) {
                wmma::load_matrix_sync(bf[j], &Bs[kk * 8][warpN * 32 + j * 16], BN + 4);
#pragma unroll
                for (int t = 0; t < bf[j].num_elements; t++)
                    bf[j].x[t] = wmma::__float_to_tf32(bf[j].x[t]);
            }
#pragma unroll
            for (int i = 0; i < 4; i++)
#pragma unroll
                for (int j = 0; j < 2; j++)
                    wmma::mma_sync(acc[i][j], af[i], bf[j], acc[i][j]);
        }
        __syncthreads();
    }

    // ---- epilogue ----
    if (!bias && !doGelu) {
#pragma unroll
        for (int i = 0; i < 4; i++)
#pragma unroll
            for (int j = 0; j < 2; j++) {
                float* Cp = C + (size_t)(bm * BM + warpM * 64 + i * 16) * Nn
                              + bn * BN + warpN * 32 + j * 16;
                wmma::store_matrix_sync(Cp, acc[i][j], Nn, wmma::mem_row_major);
            }
        return;
    }
    // fused bias+gelu: stage each 16x16 fragment in warp-private smem
    int r  = lane >> 1;             // 0..15
    int c0 = (lane & 1) * 8;        // 0 or 8
#pragma unroll
    for (int i = 0; i < 4; i++)
#pragma unroll
        for (int j = 0; j < 2; j++) {
            wmma::store_matrix_sync(&St[wid][0][0], acc[i][j], 20, wmma::mem_row_major);
            __syncwarp();
            int colbase = bn * BN + warpN * 32 + j * 16;
            int row     = bm * BM + warpM * 64 + i * 16 + r;
            float v[8];
#pragma unroll
            for (int t = 0; t < 8; t++) {
                float val = St[wid][r][c0 + t];
                if (bias) val += __ldg(&bias[colbase + c0 + t]);
                if (doGelu) val = geluf(val);
                v[t] = val;
            }
            float4* dst = (float4*)(C + (size_t)row * Nn + colbase + c0);
            dst[0] = make_float4(v[0], v[1], v[2], v[3]);
            dst[1] = make_float4(v[4], v[5], v[6], v[7]);
            __syncwarp();
        }
}

// ---------------- launch -----------------------------------------------------
extern "C" void kernel_launch(void* const* d_in, const int* in_sizes, int n_in,
                              void* d_out, int out_size) {
    const float* x  = (const float*)d_in[0];
    const void*  ei = d_in[1];                 // [2, E] src row then dst row
    const float* W1 = (const float*)d_in[2];
    const float* b1 = (const float*)d_in[3];
    const float* W2 = (const float*)d_in[4];
    const float* b2 = (const float*)d_in[5];
    const float* W3 = (const float*)d_in[6];
    const float* b3 = (const float*)d_in[7];
    const float* W4 = (const float*)d_in[8];
    const float* b4 = (const float*)d_in[9];
    float* out = (float*)d_out;

    float *bufA, *bufB;
    cudaGetSymbolAddress((void**)&bufA, g_bufA);
    cudaGetSymbolAddress((void**)&bufB, g_bufB);

    const int TB = 256;
    const int nblk   = (NN + TB - 1) / TB;
    const int eblk   = (NE + TB - 1) / TB;
    const int aggblk = 2048;

    // ---- CSR build (per launch; deterministic) ----
    detect_k<<<1, 32>>>((const long long*)ei);
    zero_k<<<nblk, TB>>>();
    count_k<<<eblk, TB>>>(ei);
    dinv_k<<<nblk, TB>>>();
    scan_k<<<1, 1024>>>();
    fill_k<<<eblk, TB>>>(ei);

    // ---- layer 1: aggregate(F=128) -> GEMM(128->512)+bias+gelu ----
    agg_kernel<1><<<aggblk, TB>>>(x, bufA, nullptr, 0);
    gemm_tf32<<<dim3(512 / 128, MPAD / 128), 256>>>(bufA, W1, bufB, 128, 512, b1, 1);

    // ---- layer 2: aggregate(F=512) -> GEMM(512->768)+bias+gelu ----
    agg_kernel<4><<<aggblk, TB>>>(bufB, bufA, nullptr, 0);
    gemm_tf32<<<dim3(768 / 128, MPAD / 128), 256>>>(bufA, W2, bufB, 512, 768, b2, 1);

    // ---- layer 3: GEMM(768->512) -> aggregate(F=512, +b3, gelu) ----
    gemm_tf32<<<dim3(512 / 128, MPAD / 128), 256>>>(bufB, W3, bufA, 768, 512, nullptr, 0);
    agg_kernel<4><<<aggblk, TB>>>(bufA, bufB, b3, 1);

    // ---- layer 4: GEMM(512->128) -> aggregate(F=128, +b4) -> out ----
    gemm_tf32<<<dim3(128 / 128, MPAD / 128), 256>>>(bufB, W4, bufA, 512, 128, nullptr, 0);
    agg_kernel<1><<<aggblk, TB>>>(bufA, out, b4, 0);
}